// round 2
// baseline (speedup 1.0000x reference)
#include <cuda_runtime.h>
#include <cstdint>

#define DEV static __device__ __forceinline__
typedef unsigned __int128 u128;

__device__ float g_s[256 * 4096];
__device__ float g_m[12 * 256];
__device__ float g_t[12 * 256];
__device__ unsigned char g_is9[10000];
__device__ unsigned char g_group[10000];
__device__ float g_bias[10000];
__device__ unsigned int g_cand[10048];
__device__ unsigned char g_accept[10048];
__device__ unsigned long long g_D[1];

// ---------------- PCG64 (numpy default_rng) ----------------
DEV u128 PCG_MULT() {
  return (((u128)0x2360ED051FC65DA4ULL) << 64) | 0x4385DF649FCCF645ULL;
}
DEV uint32_t hashmix(uint32_t v, uint32_t& hc) {
  v ^= hc; hc *= 0x931e8875u; v *= hc; v ^= v >> 16; return v;
}
DEV uint32_t mix32(uint32_t x, uint32_t y) {
  uint32_t r = 0xca01f9ddu * x - 0x4973f715u * y; r ^= r >> 16; return r;
}
DEV void pcg_seed(u128& state, u128& inc) {
  uint32_t pool[4]; uint32_t hc = 0x43b0d7e5u;
  for (int i = 0; i < 4; ++i) pool[i] = hashmix(0u, hc);
  for (int s = 0; s < 4; ++s)
    for (int d2 = 0; d2 < 4; ++d2)
      if (s != d2) pool[d2] = mix32(pool[d2], hashmix(pool[s], hc));
  uint32_t hc2 = 0x8b51f9ddu; uint32_t w[8];
  for (int i = 0; i < 8; ++i) {
    uint32_t dv = pool[i & 3];
    dv ^= hc2; hc2 *= 0x58f38dedu; dv *= hc2; dv ^= dv >> 16; w[i] = dv;
  }
  u128 initstate = (((u128)((uint64_t)w[0] | ((uint64_t)w[1] << 32))) << 64) |
                   ((uint64_t)w[2] | ((uint64_t)w[3] << 32));
  u128 initseq   = (((u128)((uint64_t)w[4] | ((uint64_t)w[5] << 32))) << 64) |
                   ((uint64_t)w[6] | ((uint64_t)w[7] << 32));
  inc = (initseq << 1) | (u128)1;
  state = inc; state += initstate;
  state = state * PCG_MULT() + inc;
}
DEV u128 pcg_advance(u128 state, u128 inc, uint64_t delta) {
  u128 cm = PCG_MULT(), cp = inc, am = (u128)1, ap = (u128)0;
  while (delta) {
    if (delta & 1) { am = am * cm; ap = ap * cm + cp; }
    cp = (cm + (u128)1) * cp; cm = cm * cm; delta >>= 1;
  }
  return am * state + ap;
}
DEV uint64_t pcg_out(u128 st) {
  unsigned rot = (unsigned)(st >> 122);
  uint64_t x = (uint64_t)(st >> 64) ^ (uint64_t)st;
  return (x >> rot) | (x << ((64 - rot) & 63));
}
DEV uint64_t draw64(u128 s0, u128 inc, uint64_t k) {
  return pcg_out(pcg_advance(s0, inc, k + 1));
}
DEV uint32_t draw32(u128 s0, u128 inc, uint64_t j) {
  uint64_t v = draw64(s0, inc, j >> 1);
  return (j & 1) ? (uint32_t)(v >> 32) : (uint32_t)v;
}

// ---------------- config kernels ----------------
__global__ void cfg1_kernel() {
  int j = blockIdx.x * blockDim.x + threadIdx.x;
  if (j >= 20048) return;
  u128 s0, inc; pcg_seed(s0, inc);
  unsigned int u = draw32(s0, inc, (uint64_t)j);
  if (j < 10000) {
    g_is9[j] = (unsigned char)(u >> 31);           // Lemire rng_excl=2
  } else {
    int c = j - 10000;                             // Lemire rng_excl=6
    unsigned long long m = (unsigned long long)u * 6ull;
    g_cand[c] = (unsigned int)(m >> 32);
    g_accept[c] = ((unsigned int)m >= 4u) ? 1 : 0;
  }
}
__global__ void cfg2_kernel() {
  __shared__ int wsum[32];
  int t = threadIdx.x;                // 1024 threads, 1 block
  const int PER = 10;
  int base = t * PER;
  unsigned char acc[PER]; int cnt = 0;
  for (int k = 0; k < PER; ++k) {
    int idx = base + k;
    unsigned char a = (idx < 10048) ? g_accept[idx] : (unsigned char)0;
    acc[k] = a; cnt += a;
  }
  int lane = t & 31, wid = t >> 5;
  int inc = cnt;
  for (int o = 1; o < 32; o <<= 1) {
    int n = __shfl_up_sync(0xffffffffu, inc, o);
    if (lane >= o) inc += n;
  }
  if (lane == 31) wsum[wid] = inc;
  __syncthreads();
  if (wid == 0) {
    int v = wsum[lane];
    for (int o = 1; o < 32; o <<= 1) {
      int n = __shfl_up_sync(0xffffffffu, v, o);
      if (lane >= o) v += n;
    }
    wsum[lane] = v;
  }
  __syncthreads();
  int excl = inc - cnt + (wid ? wsum[wid - 1] : 0);
  for (int k = 0; k < PER; ++k) {
    int idx = base + k;
    if (idx < 10048 && acc[k]) {
      if (excl < 10000) {
        g_group[excl] = (unsigned char)(g_is9[excl] * 6 + g_cand[idx]);
        if (excl == 9999) {
          unsigned long long total32 = 10000ull + (unsigned long long)(idx + 1);
          g_D[0] = (total32 + 1ull) >> 1;
        }
      }
      ++excl;
    }
  }
}
__global__ void cfg3_kernel() {
  int i = blockIdx.x * blockDim.x + threadIdx.x;
  if (i >= 10000) return;
  u128 s0, inc; pcg_seed(s0, inc);
  unsigned long long u = draw64(s0, inc, g_D[0] + (unsigned long long)i);
  double dv = (double)(u >> 11) * (1.0 / 9007199254740992.0);
  g_bias[i] = (float)(-1.0 + 2.0 * dv);
}

// ---------------- channel sum ----------------
__global__ void sum_kernel(const float* __restrict__ x) {
  int idx = blockIdx.x * blockDim.x + threadIdx.x;
  if (idx >= 256 * 1024) return;
  int b = idx >> 10, l4 = idx & 1023;
  const float4* xb = (const float4*)(x + (size_t)b * 23 * 4096) + l4;
  float4 a = xb[0];
#pragma unroll
  for (int c = 1; c < 23; ++c) {
    float4 v = xb[(size_t)c * 1024];
    a.x += v.x; a.y += v.y; a.z += v.z; a.w += v.w;
  }
  ((float4*)g_s)[(size_t)b * 1024 + l4] = a;
}

// ---------------- order-statistic helpers ----------------
DEV unsigned int f2ord(float f) {
  unsigned int b = __float_as_uint(f);
  return (b & 0x80000000u) ? ~b : (b | 0x80000000u);
}
DEV float ord2f(unsigned int k) {
  unsigned int b = (k & 0x80000000u) ? (k ^ 0x80000000u) : ~k;
  return __uint_as_float(b);
}

DEV unsigned int radix_select(const unsigned int* U, unsigned int* hist,
                              unsigned int* hist2, int* sel2, int rank, int t) {
  unsigned int prefix = 0;
  int r = rank;
  for (int pass = 0; pass < 4; ++pass) {
    int shift = 24 - pass * 8;
    unsigned int himask = (pass == 0) ? 0u : (0xFFFFFFFFu << (32 - 8 * pass));
    if (t < 256) hist[t] = 0;
    __syncthreads();
    for (int l = t; l < 4096; l += 512) {
      unsigned int key = U[l];
      bool ok = (((key ^ prefix) & himask) == 0);
      unsigned int bucket = (key >> shift) & 255u;
      unsigned int active = __ballot_sync(0xffffffffu, ok);
      if (ok) {
        unsigned int same = __match_any_sync(active, bucket);
        int leader = __ffs(same) - 1;
        if ((t & 31) == leader) atomicAdd(&hist[bucket], (unsigned int)__popc(same));
      }
    }
    __syncthreads();
    unsigned int* a = hist; unsigned int* bb = hist2;
    for (int off = 1; off < 256; off <<= 1) {
      if (t < 256) {
        unsigned int v = a[t];
        if (t >= off) v += a[t - off];
        bb[t] = v;
      }
      __syncthreads();
      unsigned int* tmp = a; a = bb; bb = tmp;
    }
    if (t < 256) {
      unsigned int lo = t ? a[t - 1] : 0u;
      unsigned int hi = a[t];
      if ((unsigned int)r >= lo && (unsigned int)r < hi) { sel2[0] = t; sel2[1] = (int)lo; }
    }
    __syncthreads();
    prefix |= ((unsigned int)sel2[0]) << shift;
    r -= sel2[1];
    __syncthreads();
  }
  return prefix;
}

DEV unsigned int next_key(const unsigned int* U, unsigned int kcur, int rank, int t,
                          unsigned int* redu, int* redc, int* sel2) {
  int lane = t & 31, wid = t >> 5;
  int cnt = 0; unsigned int mn = 0xFFFFFFFFu;
  for (int l = t; l < 4096; l += 512) {
    unsigned int key = U[l];
    cnt += (key <= kcur) ? 1 : 0;
    if (key > kcur) mn = min(mn, key);
  }
  for (int o = 16; o; o >>= 1) {
    cnt += __shfl_xor_sync(0xffffffffu, cnt, o);
    mn = min(mn, __shfl_xor_sync(0xffffffffu, mn, o));
  }
  if (lane == 0) { redu[wid] = mn; redc[wid] = cnt; }
  __syncthreads();
  if (t == 0) {
    int c = 0; unsigned int m2 = 0xFFFFFFFFu;
    for (int i = 0; i < 16; ++i) { c += redc[i]; m2 = min(m2, redu[i]); }
    sel2[0] = (c >= rank + 2) ? (int)kcur : (int)m2;
  }
  __syncthreads();
  unsigned int res = (unsigned int)sel2[0];
  __syncthreads();
  return res;
}

// ---------------- main per-(group,batch) kernel ----------------
__global__ void __launch_bounds__(512) main_kernel() {
  __shared__ __align__(16) float S[4096];
  __shared__ unsigned int U[4096];
  __shared__ unsigned int hist[256];
  __shared__ unsigned int hist2[256];
  __shared__ int sel2[2];
  __shared__ float redf[16];
  __shared__ unsigned int redu[16];
  __shared__ int redc[16];

  int g = blockIdx.x, b = blockIdx.y;
  int is9 = g / 6, dexp = g % 6;
  int K = 7 + 2 * is9, d = 1 << dexp;
  int pad = ((K - 1) * d) >> 1;
  int t = threadIdx.x, lane = t & 31, wid = t >> 5;

  const float4* src = (const float4*)(g_s + (size_t)b * 4096);
  for (int i = t; i < 1024; i += 512) ((float4*)S)[i] = src[i];
  __syncthreads();

  float mx = -3.402823466e38f;
  for (int l = t; l < 4096; l += 512) {
    float acc = 0.f;
    int j = l - pad;
    for (int k = 0; k < K; ++k) {
      int jj = j + k * d;
      float v = (jj >= 0 && jj < 4096) ? S[jj] : 0.f;
      acc += v;
    }
    mx = fmaxf(mx, acc);
    U[l] = f2ord(acc);
  }
  for (int o = 16; o; o >>= 1) mx = fmaxf(mx, __shfl_xor_sync(0xffffffffu, mx, o));
  if (lane == 0) redf[wid] = mx;
  __syncthreads();
  if (t == 0) {
    float bm = redf[0];
    for (int i = 1; i < 16; ++i) bm = fmaxf(bm, redf[i]);
    g_m[g * 256 + b] = bm;
  }
  __syncthreads();

  unsigned int k1351 = radix_select(U, hist, hist2, sel2, 1351, t);
  unsigned int k1352 = next_key(U, k1351, 1351, t, redu, redc, sel2);
  unsigned int k2702 = radix_select(U, hist, hist2, sel2, 2702, t);
  unsigned int k2703 = next_key(U, k2702, 2702, t, redu, redc, sel2);

  if (t == 0) {
    float v1351 = ord2f(k1351), v1352 = ord2f(k1352);
    float v2702 = ord2f(k2702), v2703 = ord2f(k2703);
    float qp33 = 0.33f * 4095.0f;
    float qp66 = 0.66f * 4095.0f;
    float hw33 = qp33 - 1351.0f, lw33 = 1.0f - hw33;
    float hw66 = qp66 - 2702.0f, lw66 = 1.0f - hw66;
    float q33 = v1351 * lw33 + v1352 * hw33;
    float q66 = v2702 * lw66 + v2703 * hw66;
    g_t[g * 256 + b] = (q66 - q33 > 0.0f) ? 1.0f : 0.0f;
  }
}

// ---------------- output writer ----------------
__global__ void out_kernel(float* __restrict__ out) {
  int idx = blockIdx.x * blockDim.x + threadIdx.x;   // b*10000 + i
  if (idx >= 2560000) return;
  int b = idx / 10000;
  int i = idx - b * 10000;
  int g = g_group[i];
  float f1 = (g_m[g * 256 + b] > g_bias[i]) ? 1.0f : 0.0f;
  float f2 = g_t[g * 256 + b];
  ((float2*)out)[idx] = make_float2(f1, f2);
}

extern "C" void kernel_launch(void* const* d_in, const int* in_sizes, int n_in,
                              void* d_out, int out_size) {
  const float* x = (const float*)d_in[0];
  float* out = (float*)d_out;
  cfg1_kernel<<<(20048 + 255) / 256, 256>>>();
  cfg2_kernel<<<1, 1024>>>();
  cfg3_kernel<<<(10000 + 255) / 256, 256>>>();
  sum_kernel<<<(256 * 1024 + 255) / 256, 256>>>(x);
  main_kernel<<<dim3(12, 256), 512>>>();
  out_kernel<<<(2560000 + 255) / 256, 256>>>(out);
}

// round 3
// speedup vs baseline: 2.1275x; 2.1275x over previous
#include <cuda_runtime.h>
#include <cstdint>

#define DEV static __device__ __forceinline__
typedef unsigned __int128 u128;

__device__ float g_s[256 * 4096];
__device__ float g_m[12 * 256];
__device__ float g_t[12 * 256];
__device__ unsigned char g_is9[10000];
__device__ unsigned char g_group[10000];
__device__ float g_bias[10000];
__device__ unsigned int g_cand[10048];
__device__ unsigned char g_accept[10048];
__device__ unsigned long long g_D[1];

// ---------------- PCG64 (numpy default_rng) ----------------
DEV u128 PCG_MULT() {
  return (((u128)0x2360ED051FC65DA4ULL) << 64) | 0x4385DF649FCCF645ULL;
}
DEV uint32_t hashmix(uint32_t v, uint32_t& hc) {
  v ^= hc; hc *= 0x931e8875u; v *= hc; v ^= v >> 16; return v;
}
DEV uint32_t mix32(uint32_t x, uint32_t y) {
  uint32_t r = 0xca01f9ddu * x - 0x4973f715u * y; r ^= r >> 16; return r;
}
DEV void pcg_seed(u128& state, u128& inc) {
  uint32_t pool[4]; uint32_t hc = 0x43b0d7e5u;
  for (int i = 0; i < 4; ++i) pool[i] = hashmix(0u, hc);
  for (int s = 0; s < 4; ++s)
    for (int d2 = 0; d2 < 4; ++d2)
      if (s != d2) pool[d2] = mix32(pool[d2], hashmix(pool[s], hc));
  uint32_t hc2 = 0x8b51f9ddu; uint32_t w[8];
  for (int i = 0; i < 8; ++i) {
    uint32_t dv = pool[i & 3];
    dv ^= hc2; hc2 *= 0x58f38dedu; dv *= hc2; dv ^= dv >> 16; w[i] = dv;
  }
  u128 initstate = (((u128)((uint64_t)w[0] | ((uint64_t)w[1] << 32))) << 64) |
                   ((uint64_t)w[2] | ((uint64_t)w[3] << 32));
  u128 initseq   = (((u128)((uint64_t)w[4] | ((uint64_t)w[5] << 32))) << 64) |
                   ((uint64_t)w[6] | ((uint64_t)w[7] << 32));
  inc = (initseq << 1) | (u128)1;
  state = inc; state += initstate;
  state = state * PCG_MULT() + inc;
}
DEV u128 pcg_advance(u128 state, u128 inc, uint64_t delta) {
  u128 cm = PCG_MULT(), cp = inc, am = (u128)1, ap = (u128)0;
  while (delta) {
    if (delta & 1) { am = am * cm; ap = ap * cm + cp; }
    cp = (cm + (u128)1) * cp; cm = cm * cm; delta >>= 1;
  }
  return am * state + ap;
}
DEV uint64_t pcg_out(u128 st) {
  unsigned rot = (unsigned)(st >> 122);
  uint64_t x = (uint64_t)(st >> 64) ^ (uint64_t)st;
  return (x >> rot) | (x << ((64 - rot) & 63));
}
DEV uint64_t draw64(u128 s0, u128 inc, uint64_t k) {
  return pcg_out(pcg_advance(s0, inc, k + 1));
}
DEV uint32_t draw32(u128 s0, u128 inc, uint64_t j) {
  uint64_t v = draw64(s0, inc, j >> 1);
  return (j & 1) ? (uint32_t)(v >> 32) : (uint32_t)v;
}

// ---------------- config kernels ----------------
__global__ void cfg1_kernel() {
  int j = blockIdx.x * blockDim.x + threadIdx.x;
  if (j >= 20048) return;
  u128 s0, inc; pcg_seed(s0, inc);
  unsigned int u = draw32(s0, inc, (uint64_t)j);
  if (j < 10000) {
    g_is9[j] = (unsigned char)(u >> 31);           // Lemire rng_excl=2
  } else {
    int c = j - 10000;                             // Lemire rng_excl=6
    unsigned long long m = (unsigned long long)u * 6ull;
    g_cand[c] = (unsigned int)(m >> 32);
    g_accept[c] = ((unsigned int)m >= 4u) ? 1 : 0;
  }
}
__global__ void cfg2_kernel() {
  __shared__ int wsum[32];
  int t = threadIdx.x;                // 1024 threads, 1 block
  const int PER = 10;
  int base = t * PER;
  unsigned char acc[PER]; int cnt = 0;
  for (int k = 0; k < PER; ++k) {
    int idx = base + k;
    unsigned char a = (idx < 10048) ? g_accept[idx] : (unsigned char)0;
    acc[k] = a; cnt += a;
  }
  int lane = t & 31, wid = t >> 5;
  int inc = cnt;
  for (int o = 1; o < 32; o <<= 1) {
    int n = __shfl_up_sync(0xffffffffu, inc, o);
    if (lane >= o) inc += n;
  }
  if (lane == 31) wsum[wid] = inc;
  __syncthreads();
  if (wid == 0) {
    int v = wsum[lane];
    for (int o = 1; o < 32; o <<= 1) {
      int n = __shfl_up_sync(0xffffffffu, v, o);
      if (lane >= o) v += n;
    }
    wsum[lane] = v;
  }
  __syncthreads();
  int excl = inc - cnt + (wid ? wsum[wid - 1] : 0);
  for (int k = 0; k < PER; ++k) {
    int idx = base + k;
    if (idx < 10048 && acc[k]) {
      if (excl < 10000) {
        g_group[excl] = (unsigned char)(g_is9[excl] * 6 + g_cand[idx]);
        if (excl == 9999) {
          unsigned long long total32 = 10000ull + (unsigned long long)(idx + 1);
          g_D[0] = (total32 + 1ull) >> 1;
        }
      }
      ++excl;
    }
  }
}
__global__ void cfg3_kernel() {
  int i = blockIdx.x * blockDim.x + threadIdx.x;
  if (i >= 10000) return;
  u128 s0, inc; pcg_seed(s0, inc);
  unsigned long long u = draw64(s0, inc, g_D[0] + (unsigned long long)i);
  double dv = (double)(u >> 11) * (1.0 / 9007199254740992.0);
  g_bias[i] = (float)(-1.0 + 2.0 * dv);
}

// ---------------- channel sum ----------------
__global__ void sum_kernel(const float* __restrict__ x) {
  int idx = blockIdx.x * blockDim.x + threadIdx.x;
  if (idx >= 256 * 1024) return;
  int b = idx >> 10, l4 = idx & 1023;
  const float4* xb = (const float4*)(x + (size_t)b * 23 * 4096) + l4;
  float4 a = xb[0];
#pragma unroll
  for (int c = 1; c < 23; ++c) {
    float4 v = xb[(size_t)c * 1024];
    a.x += v.x; a.y += v.y; a.z += v.z; a.w += v.w;
  }
  ((float4*)g_s)[(size_t)b * 1024 + l4] = a;
}

// ---------------- order-statistic helpers ----------------
DEV unsigned int f2ord(float f) {
  unsigned int b = __float_as_uint(f);
  return (b & 0x80000000u) ? ~b : (b | 0x80000000u);
}
DEV float ord2f(unsigned int k) {
  unsigned int b = (k & 0x80000000u) ? (k ^ 0x80000000u) : ~k;
  return __uint_as_float(b);
}

// ---------------- main per-(group,batch) kernel ----------------
// 256 threads, 16 elements/thread. Dual-rank merged radix select.
__global__ void __launch_bounds__(256) main_kernel() {
  __shared__ __align__(16) unsigned int U[4096];   // aliased: float S first
  __shared__ unsigned int histA[256], histB[256];
  __shared__ unsigned int wtA[8], wtB[8];
  __shared__ int selA[2], selB[2];
  __shared__ float redf[8];
  __shared__ unsigned int rmA[8], rmB[8];
  __shared__ int rcA[8], rcB[8];

  int g = blockIdx.x, b = blockIdx.y;
  int is9 = g / 6, dexp = g % 6;
  int K = 7 + 2 * is9, d = 1 << dexp;
  int pad = ((K - 1) * d) >> 1;
  int t = threadIdx.x, lane = t & 31, wid = t >> 5;

  // load s row into smem (as float), zero histA
  float* S = (float*)U;
  histA[t] = 0;
  {
    const float4* src = (const float4*)(g_s + (size_t)b * 4096);
#pragma unroll
    for (int i = 0; i < 4; ++i) ((float4*)S)[t + i * 256] = src[t + i * 256];
  }
  __syncthreads();

  // conv into registers
  float racc[16];
#pragma unroll
  for (int i = 0; i < 16; ++i) {
    int l = t + i * 256;
    int j0 = l - pad;
    float acc = 0.f;
    for (int k = 0; k < K; ++k) {
      int jj = j0 + k * d;
      if (jj >= 0 && jj < 4096) acc += S[jj];
    }
    racc[i] = acc;
  }
  __syncthreads();

  // write keys (overwriting S), build pass-0 histogram, block max
  float mx = -3.402823466e38f;
#pragma unroll
  for (int i = 0; i < 16; ++i) {
    int l = t + i * 256;
    float acc = racc[i];
    mx = fmaxf(mx, acc);
    unsigned int key = f2ord(acc);
    U[l] = key;
    unsigned int bucket = key >> 24;
    unsigned int same = __match_any_sync(0xffffffffu, bucket);
    int ldr = __ffs(same) - 1;
    if (lane == ldr) atomicAdd(&histA[bucket], (unsigned int)__popc(same));
  }
  for (int o = 16; o; o >>= 1) mx = fmaxf(mx, __shfl_xor_sync(0xffffffffu, mx, o));
  if (lane == 0) redf[wid] = mx;
  __syncthreads();

  unsigned int pA = 0, pB = 0;
  int rA = 1351, rB = 2702;

  // dual scan + select over histA/histB (pass0: both from histA)
#define DUAL_SCAN_SELECT(HA, HB)                                              \
  {                                                                            \
    unsigned int oa = (HA)[t], ob = (HB)[t];                                   \
    unsigned int a = oa, bb2 = ob;                                             \
    for (int o = 1; o < 32; o <<= 1) {                                         \
      unsigned int na = __shfl_up_sync(0xffffffffu, a, o);                     \
      unsigned int nb = __shfl_up_sync(0xffffffffu, bb2, o);                   \
      if (lane >= o) { a += na; bb2 += nb; }                                   \
    }                                                                          \
    if (lane == 31) { wtA[wid] = a; wtB[wid] = bb2; }                          \
    __syncthreads();                                                           \
    if (wid == 0) {                                                            \
      unsigned int va = (lane < 8) ? wtA[lane] : 0u;                           \
      unsigned int vb = (lane < 8) ? wtB[lane] : 0u;                           \
      for (int o = 1; o < 8; o <<= 1) {                                        \
        unsigned int na = __shfl_up_sync(0xffffffffu, va, o);                  \
        unsigned int nb = __shfl_up_sync(0xffffffffu, vb, o);                  \
        if (lane >= o) { va += na; vb += nb; }                                 \
      }                                                                        \
      if (lane < 8) { wtA[lane] = va; wtB[lane] = vb; }                        \
    }                                                                          \
    __syncthreads();                                                           \
    unsigned int offA = wid ? wtA[wid - 1] : 0u;                               \
    unsigned int offB = wid ? wtB[wid - 1] : 0u;                               \
    a += offA; bb2 += offB;                                                    \
    unsigned int loA = a - oa, loB = bb2 - ob;                                 \
    if ((unsigned)rA >= loA && (unsigned)rA < a) { selA[0] = t; selA[1] = (int)loA; } \
    if ((unsigned)rB >= loB && (unsigned)rB < bb2) { selB[0] = t; selB[1] = (int)loB; } \
    __syncthreads();                                                           \
  }

  DUAL_SCAN_SELECT(histA, histA);
  pA = ((unsigned int)selA[0]) << 24; rA -= selA[1];
  pB = ((unsigned int)selB[0]) << 24; rB -= selB[1];

  for (int p = 1; p < 4; ++p) {
    int shift = 24 - 8 * p;
    unsigned int maskHi = 0xFFFFFFFFu << (32 - 8 * p);
    histA[t] = 0; histB[t] = 0;
    __syncthreads();
#pragma unroll
    for (int i = 0; i < 16; ++i) {
      unsigned int key = U[t + i * 256];
      unsigned int bucket = (key >> shift) & 255u;
      bool okA = ((key ^ pA) & maskHi) == 0;
      bool okB = ((key ^ pB) & maskHi) == 0;
      unsigned int actA = __ballot_sync(0xffffffffu, okA);
      if (okA) {
        unsigned int same = __match_any_sync(actA, bucket);
        int ldr = __ffs(same) - 1;
        if (lane == ldr) atomicAdd(&histA[bucket], (unsigned int)__popc(same));
      }
      unsigned int actB = __ballot_sync(0xffffffffu, okB);
      if (okB) {
        unsigned int same = __match_any_sync(actB, bucket);
        int ldr = __ffs(same) - 1;
        if (lane == ldr) atomicAdd(&histB[bucket], (unsigned int)__popc(same));
      }
    }
    __syncthreads();
    DUAL_SCAN_SELECT(histA, histB);
    pA |= ((unsigned int)selA[0]) << shift; rA -= selA[1];
    pB |= ((unsigned int)selB[0]) << shift; rB -= selB[1];
  }

  // merged next-key pass: counts(<=k) and min(>k) for both keys
  unsigned int kA = pA, kB = pB;
  int cA = 0, cB = 0;
  unsigned int mnA = 0xFFFFFFFFu, mnB = 0xFFFFFFFFu;
#pragma unroll
  for (int i = 0; i < 16; ++i) {
    unsigned int key = U[t + i * 256];
    if (key <= kA) ++cA; else mnA = min(mnA, key);
    if (key <= kB) ++cB; else mnB = min(mnB, key);
  }
  for (int o = 16; o; o >>= 1) {
    cA += __shfl_xor_sync(0xffffffffu, cA, o);
    cB += __shfl_xor_sync(0xffffffffu, cB, o);
    mnA = min(mnA, __shfl_xor_sync(0xffffffffu, mnA, o));
    mnB = min(mnB, __shfl_xor_sync(0xffffffffu, mnB, o));
  }
  if (lane == 0) { rcA[wid] = cA; rcB[wid] = cB; rmA[wid] = mnA; rmB[wid] = mnB; }
  __syncthreads();

  if (t == 0) {
    int tcA = 0, tcB = 0;
    unsigned int tmA = 0xFFFFFFFFu, tmB = 0xFFFFFFFFu;
    float bm = redf[0];
#pragma unroll
    for (int i = 0; i < 8; ++i) {
      tcA += rcA[i]; tcB += rcB[i];
      tmA = min(tmA, rmA[i]); tmB = min(tmB, rmB[i]);
      bm = fmaxf(bm, redf[i]);
    }
    unsigned int k1352 = (tcA >= 1353) ? kA : tmA;
    unsigned int k2703 = (tcB >= 2704) ? kB : tmB;
    float v1351 = ord2f(kA), v1352 = ord2f(k1352);
    float v2702 = ord2f(kB), v2703 = ord2f(k2703);
    float qp33 = 0.33f * 4095.0f;
    float qp66 = 0.66f * 4095.0f;
    float hw33 = qp33 - 1351.0f, lw33 = 1.0f - hw33;
    float hw66 = qp66 - 2702.0f, lw66 = 1.0f - hw66;
    float q33 = v1351 * lw33 + v1352 * hw33;
    float q66 = v2702 * lw66 + v2703 * hw66;
    g_m[g * 256 + b] = bm;
    g_t[g * 256 + b] = (q66 - q33 > 0.0f) ? 1.0f : 0.0f;
  }
}

// ---------------- output writer (float4 = 2 feature pairs) ----------------
__global__ void out_kernel(float* __restrict__ out) {
  int idx = blockIdx.x * blockDim.x + threadIdx.x;   // b*5000 + j
  if (idx >= 1280000) return;
  int b = idx / 5000;
  int j = idx - b * 5000;
  int i0 = 2 * j, i1 = 2 * j + 1;
  int g0 = g_group[i0], g1 = g_group[i1];
  float4 v;
  v.x = (g_m[g0 * 256 + b] > g_bias[i0]) ? 1.0f : 0.0f;
  v.y = g_t[g0 * 256 + b];
  v.z = (g_m[g1 * 256 + b] > g_bias[i1]) ? 1.0f : 0.0f;
  v.w = g_t[g1 * 256 + b];
  ((float4*)out)[idx] = v;
}

extern "C" void kernel_launch(void* const* d_in, const int* in_sizes, int n_in,
                              void* d_out, int out_size) {
  const float* x = (const float*)d_in[0];
  float* out = (float*)d_out;
  cfg1_kernel<<<(20048 + 255) / 256, 256>>>();
  cfg2_kernel<<<1, 1024>>>();
  cfg3_kernel<<<(10000 + 255) / 256, 256>>>();
  sum_kernel<<<(256 * 1024 + 255) / 256, 256>>>(x);
  main_kernel<<<dim3(12, 256), 256>>>();
  out_kernel<<<(1280000 + 255) / 256, 256>>>(out);
}

// round 4
// speedup vs baseline: 4.4145x; 2.0749x over previous
#include <cuda_runtime.h>
#include <cstdint>

#define DEV static __device__ __forceinline__
typedef unsigned __int128 u128;

__device__ float g_s[256 * 4096];
__device__ float g_m[256 * 12];
__device__ float g_t[256 * 12];
__device__ unsigned char g_is9[10000];
__device__ unsigned char g_group[10000];
__device__ float g_bias[10000];
__device__ unsigned int g_cand[10048];
__device__ unsigned char g_accept[10048];
__device__ unsigned long long g_D[1];

// ---------------- PCG64 (numpy default_rng) ----------------
DEV u128 PCG_MULT() {
  return (((u128)0x2360ED051FC65DA4ULL) << 64) | 0x4385DF649FCCF645ULL;
}
DEV uint32_t hashmix(uint32_t v, uint32_t& hc) {
  v ^= hc; hc *= 0x931e8875u; v *= hc; v ^= v >> 16; return v;
}
DEV uint32_t mix32(uint32_t x, uint32_t y) {
  uint32_t r = 0xca01f9ddu * x - 0x4973f715u * y; r ^= r >> 16; return r;
}
DEV void pcg_seed(u128& state, u128& inc) {
  uint32_t pool[4]; uint32_t hc = 0x43b0d7e5u;
  for (int i = 0; i < 4; ++i) pool[i] = hashmix(0u, hc);
  for (int s = 0; s < 4; ++s)
    for (int d2 = 0; d2 < 4; ++d2)
      if (s != d2) pool[d2] = mix32(pool[d2], hashmix(pool[s], hc));
  uint32_t hc2 = 0x8b51f9ddu; uint32_t w[8];
  for (int i = 0; i < 8; ++i) {
    uint32_t dv = pool[i & 3];
    dv ^= hc2; hc2 *= 0x58f38dedu; dv *= hc2; dv ^= dv >> 16; w[i] = dv;
  }
  u128 initstate = (((u128)((uint64_t)w[0] | ((uint64_t)w[1] << 32))) << 64) |
                   ((uint64_t)w[2] | ((uint64_t)w[3] << 32));
  u128 initseq   = (((u128)((uint64_t)w[4] | ((uint64_t)w[5] << 32))) << 64) |
                   ((uint64_t)w[6] | ((uint64_t)w[7] << 32));
  inc = (initseq << 1) | (u128)1;
  state = inc; state += initstate;
  state = state * PCG_MULT() + inc;
}
DEV u128 pcg_advance(u128 state, u128 inc, uint64_t delta) {
  u128 cm = PCG_MULT(), cp = inc, am = (u128)1, ap = (u128)0;
  while (delta) {
    if (delta & 1) { am = am * cm; ap = ap * cm + cp; }
    cp = (cm + (u128)1) * cp; cm = cm * cm; delta >>= 1;
  }
  return am * state + ap;
}
DEV uint64_t pcg_out(u128 st) {
  unsigned rot = (unsigned)(st >> 122);
  uint64_t x = (uint64_t)(st >> 64) ^ (uint64_t)st;
  return (x >> rot) | (x << ((64 - rot) & 63));
}
DEV uint64_t draw64(u128 s0, u128 inc, uint64_t k) {
  return pcg_out(pcg_advance(s0, inc, k + 1));
}
DEV uint32_t draw32(u128 s0, u128 inc, uint64_t j) {
  uint64_t v = draw64(s0, inc, j >> 1);
  return (j & 1) ? (uint32_t)(v >> 32) : (uint32_t)v;
}

// ---------------- config kernels ----------------
__global__ void cfg1_kernel() {
  int j = blockIdx.x * blockDim.x + threadIdx.x;
  if (j >= 20048) return;
  u128 s0, inc; pcg_seed(s0, inc);
  unsigned int u = draw32(s0, inc, (uint64_t)j);
  if (j < 10000) {
    g_is9[j] = (unsigned char)(u >> 31);           // Lemire rng_excl=2
  } else {
    int c = j - 10000;                             // Lemire rng_excl=6
    unsigned long long m = (unsigned long long)u * 6ull;
    g_cand[c] = (unsigned int)(m >> 32);
    g_accept[c] = ((unsigned int)m >= 4u) ? 1 : 0;
  }
}
__global__ void cfg2_kernel() {
  __shared__ int wsum[32];
  int t = threadIdx.x;                // 1024 threads, 1 block
  const int PER = 10;
  int base = t * PER;
  unsigned char acc[PER]; int cnt = 0;
  for (int k = 0; k < PER; ++k) {
    int idx = base + k;
    unsigned char a = (idx < 10048) ? g_accept[idx] : (unsigned char)0;
    acc[k] = a; cnt += a;
  }
  int lane = t & 31, wid = t >> 5;
  int inc = cnt;
  for (int o = 1; o < 32; o <<= 1) {
    int n = __shfl_up_sync(0xffffffffu, inc, o);
    if (lane >= o) inc += n;
  }
  if (lane == 31) wsum[wid] = inc;
  __syncthreads();
  if (wid == 0) {
    int v = wsum[lane];
    for (int o = 1; o < 32; o <<= 1) {
      int n = __shfl_up_sync(0xffffffffu, v, o);
      if (lane >= o) v += n;
    }
    wsum[lane] = v;
  }
  __syncthreads();
  int excl = inc - cnt + (wid ? wsum[wid - 1] : 0);
  for (int k = 0; k < PER; ++k) {
    int idx = base + k;
    if (idx < 10048 && acc[k]) {
      if (excl < 10000) {
        g_group[excl] = (unsigned char)(g_is9[excl] * 6 + g_cand[idx]);
        if (excl == 9999) {
          unsigned long long total32 = 10000ull + (unsigned long long)(idx + 1);
          g_D[0] = (total32 + 1ull) >> 1;
        }
      }
      ++excl;
    }
  }
}
__global__ void cfg3_kernel() {
  int i = blockIdx.x * blockDim.x + threadIdx.x;
  if (i >= 10000) return;
  u128 s0, inc; pcg_seed(s0, inc);
  unsigned long long u = draw64(s0, inc, g_D[0] + (unsigned long long)i);
  double dv = (double)(u >> 11) * (1.0 / 9007199254740992.0);
  g_bias[i] = (float)(-1.0 + 2.0 * dv);
}

// ---------------- channel sum ----------------
__global__ void sum_kernel(const float* __restrict__ x) {
  int idx = blockIdx.x * blockDim.x + threadIdx.x;   // 0..131071, float4-pair units
  if (idx >= 256 * 512) return;
  int b = idx >> 9, l8 = idx & 511;
  const float4* xb = (const float4*)(x + (size_t)b * 23 * 4096) + l8 * 2;
  float4 a0 = xb[0], a1 = xb[1];
#pragma unroll
  for (int c = 1; c < 23; ++c) {
    float4 v0 = xb[(size_t)c * 1024];
    float4 v1 = xb[(size_t)c * 1024 + 1];
    a0.x += v0.x; a0.y += v0.y; a0.z += v0.z; a0.w += v0.w;
    a1.x += v1.x; a1.y += v1.y; a1.z += v1.z; a1.w += v1.w;
  }
  float4* dst = (float4*)g_s + (size_t)b * 1024 + l8 * 2;
  dst[0] = a0; dst[1] = a1;
}

// ---------------- order-statistic helpers ----------------
DEV unsigned int f2ord(float f) {
  unsigned int b = __float_as_uint(f);
  return (b & 0x80000000u) ? ~b : (b | 0x80000000u);
}

template <int K, int D>
DEV void conv16(const float* S, int t, float* racc) {
  const int pad = ((K - 1) * D) >> 1;
#pragma unroll
  for (int i = 0; i < 16; ++i) {
    int s0 = t + i * 256 + 128 - pad;
    float acc = 0.f;
#pragma unroll
    for (int k = 0; k < K; ++k) acc += S[s0 + k * D];
    racc[i] = acc;
  }
}

// ---------------- main per-(batch,group) kernel ----------------
// 256 threads, 16 elements/thread. Hot path: conv + max + pass0 histogram;
// flag=1 certified if no 8-bit bucket holds >=1353 keys (a 1353-duplicate
// value is required for q66==q33). Exact radix-select fallback otherwise.
__global__ void __launch_bounds__(256) main_kernel() {
  __shared__ __align__(16) unsigned int buf[4352];  // pad128 | data4096 | pad128
  __shared__ unsigned int histA[256];
  __shared__ unsigned int wt[8];
  __shared__ int sel[2];
  __shared__ float redf[8];
  __shared__ unsigned int smax[8];
  __shared__ int rci[8];

  int b = blockIdx.x, g = blockIdx.y;
  int t = threadIdx.x, lane = t & 31, wid = t >> 5;

  float* S = (float*)buf;
  unsigned int* U = buf + 128;

  histA[t] = 0;
  if (t < 128) buf[t] = 0; else buf[4096 + t] = 0;   // zero both pads
  {
    const float4* src = (const float4*)(g_s + (size_t)b * 4096);
    float4* dstS = (float4*)(S + 128);
#pragma unroll
    for (int i = 0; i < 4; ++i) dstS[t + i * 256] = src[t + i * 256];
  }
  __syncthreads();

  float racc[16];
  switch (g) {
    case 0:  conv16<7, 1>(S, t, racc);  break;
    case 1:  conv16<7, 2>(S, t, racc);  break;
    case 2:  conv16<7, 4>(S, t, racc);  break;
    case 3:  conv16<7, 8>(S, t, racc);  break;
    case 4:  conv16<7, 16>(S, t, racc); break;
    case 5:  conv16<7, 32>(S, t, racc); break;
    case 6:  conv16<9, 1>(S, t, racc);  break;
    case 7:  conv16<9, 2>(S, t, racc);  break;
    case 8:  conv16<9, 4>(S, t, racc);  break;
    case 9:  conv16<9, 8>(S, t, racc);  break;
    case 10: conv16<9, 16>(S, t, racc); break;
    default: conv16<9, 32>(S, t, racc); break;
  }
  __syncthreads();

  // write keys (overwriting S data region), pass-0 histogram, block max
  float mx = -3.402823466e38f;
#pragma unroll
  for (int i = 0; i < 16; ++i) {
    float acc = racc[i];
    mx = fmaxf(mx, acc);
    unsigned int key = f2ord(acc);
    U[t + i * 256] = key;
    unsigned int bucket = key >> 24;
    unsigned int same = __match_any_sync(0xffffffffu, bucket);
    int ldr = __ffs(same) - 1;
    if (lane == ldr) atomicAdd(&histA[bucket], (unsigned int)__popc(same));
  }
  for (int o = 16; o; o >>= 1) mx = fmaxf(mx, __shfl_xor_sync(0xffffffffu, mx, o));
  if (lane == 0) redf[wid] = mx;
  __syncthreads();

  // max bucket count
  unsigned int hv = histA[t];
  for (int o = 16; o; o >>= 1) hv = max(hv, __shfl_xor_sync(0xffffffffu, hv, o));
  if (lane == 0) smax[wid] = hv;
  __syncthreads();
  unsigned int mb = 0;
#pragma unroll
  for (int i = 0; i < 8; ++i) mb = max(mb, smax[i]);

  if (mb < 1353u) {                 // certified: no value has 1353 duplicates
    if (t == 0) {
      float bm = redf[0];
#pragma unroll
      for (int i = 1; i < 8; ++i) bm = fmaxf(bm, redf[i]);
      g_m[b * 12 + g] = bm;
      g_t[b * 12 + g] = 1.0f;
    }
    return;
  }

  // ---- exact fallback: radix-select rank 1351, then count(<= key) ----
#define SCAN_SELECT(rr)                                                        \
  {                                                                            \
    unsigned int oa = histA[t]; unsigned int a = oa;                           \
    for (int o = 1; o < 32; o <<= 1) {                                         \
      unsigned int na = __shfl_up_sync(0xffffffffu, a, o);                     \
      if (lane >= o) a += na;                                                  \
    }                                                                          \
    if (lane == 31) wt[wid] = a;                                               \
    __syncthreads();                                                           \
    if (wid == 0) {                                                            \
      unsigned int va = (lane < 8) ? wt[lane] : 0u;                            \
      for (int o = 1; o < 8; o <<= 1) {                                        \
        unsigned int na = __shfl_up_sync(0xffffffffu, va, o);                  \
        if (lane >= o) va += na;                                               \
      }                                                                        \
      if (lane < 8) wt[lane] = va;                                             \
    }                                                                          \
    __syncthreads();                                                           \
    a += wid ? wt[wid - 1] : 0u;                                               \
    unsigned int lo = a - oa;                                                  \
    if ((unsigned)(rr) >= lo && (unsigned)(rr) < a) { sel[0] = t; sel[1] = (int)lo; } \
    __syncthreads();                                                           \
  }

  int rA = 1351; unsigned int pA = 0;
  SCAN_SELECT(rA);
  pA = ((unsigned int)sel[0]) << 24; rA -= sel[1];

  for (int p = 1; p < 4; ++p) {
    int shift = 24 - 8 * p;
    unsigned int maskHi = 0xFFFFFFFFu << (32 - 8 * p);
    histA[t] = 0;
    __syncthreads();
#pragma unroll
    for (int i = 0; i < 16; ++i) {
      unsigned int key = U[t + i * 256];
      bool ok = ((key ^ pA) & maskHi) == 0;
      unsigned int bucket = (key >> shift) & 255u;
      unsigned int act = __ballot_sync(0xffffffffu, ok);
      if (ok) {
        unsigned int same = __match_any_sync(act, bucket);
        int ldr = __ffs(same) - 1;
        if (lane == ldr) atomicAdd(&histA[bucket], (unsigned int)__popc(same));
      }
    }
    __syncthreads();
    SCAN_SELECT(rA);
    pA |= ((unsigned int)sel[0]) << shift; rA -= sel[1];
  }

  int cnt = 0;
#pragma unroll
  for (int i = 0; i < 16; ++i) cnt += (U[t + i * 256] <= pA) ? 1 : 0;
  for (int o = 16; o; o >>= 1) cnt += __shfl_xor_sync(0xffffffffu, cnt, o);
  if (lane == 0) rci[wid] = cnt;
  __syncthreads();
  if (t == 0) {
    int total = 0;
    float bm = redf[0];
#pragma unroll
    for (int i = 0; i < 8; ++i) { total += rci[i]; bm = fmaxf(bm, redf[i]); }
    g_m[b * 12 + g] = bm;
    g_t[b * 12 + g] = (total < 2704) ? 1.0f : 0.0f;   // v[1351] < v[2703]
  }
}

// ---------------- output writer (float4 = 2 feature pairs) ----------------
__global__ void out_kernel(float* __restrict__ out) {
  int idx = blockIdx.x * blockDim.x + threadIdx.x;   // b*5000 + j
  if (idx >= 1280000) return;
  int b = idx / 5000;
  int j = idx - b * 5000;
  int i0 = 2 * j, i1 = 2 * j + 1;
  int g0 = g_group[i0], g1 = g_group[i1];
  float4 v;
  v.x = (g_m[b * 12 + g0] > g_bias[i0]) ? 1.0f : 0.0f;
  v.y = g_t[b * 12 + g0];
  v.z = (g_m[b * 12 + g1] > g_bias[i1]) ? 1.0f : 0.0f;
  v.w = g_t[b * 12 + g1];
  ((float4*)out)[idx] = v;
}

extern "C" void kernel_launch(void* const* d_in, const int* in_sizes, int n_in,
                              void* d_out, int out_size) {
  const float* x = (const float*)d_in[0];
  float* out = (float*)d_out;
  cfg1_kernel<<<(20048 + 255) / 256, 256>>>();
  cfg2_kernel<<<1, 1024>>>();
  cfg3_kernel<<<(10000 + 255) / 256, 256>>>();
  sum_kernel<<<(256 * 512 + 255) / 256, 256>>>(x);
  main_kernel<<<dim3(256, 12), 256>>>();
  out_kernel<<<(1280000 + 255) / 256, 256>>>(out);
}

// round 5
// speedup vs baseline: 4.4290x; 1.0033x over previous
#include <cuda_runtime.h>
#include <cstdint>

#define DEV static __device__ __forceinline__
typedef unsigned __int128 u128;

__device__ float g_s[256 * 4096];
__device__ float g_m[256 * 12];
__device__ float g_t[256 * 12];
__device__ unsigned char g_is9[10000];
__device__ unsigned char g_group[10000];
__device__ float g_bias[10000];
__device__ unsigned int g_cand[10048];
__device__ unsigned char g_accept[10048];
__device__ unsigned long long g_D[1];

// ---------------- PCG64 (numpy default_rng) ----------------
DEV u128 PCG_MULT() {
  return (((u128)0x2360ED051FC65DA4ULL) << 64) | 0x4385DF649FCCF645ULL;
}
DEV uint32_t hashmix(uint32_t v, uint32_t& hc) {
  v ^= hc; hc *= 0x931e8875u; v *= hc; v ^= v >> 16; return v;
}
DEV uint32_t mix32(uint32_t x, uint32_t y) {
  uint32_t r = 0xca01f9ddu * x - 0x4973f715u * y; r ^= r >> 16; return r;
}
DEV void pcg_seed(u128& state, u128& inc) {
  uint32_t pool[4]; uint32_t hc = 0x43b0d7e5u;
  for (int i = 0; i < 4; ++i) pool[i] = hashmix(0u, hc);
  for (int s = 0; s < 4; ++s)
    for (int d2 = 0; d2 < 4; ++d2)
      if (s != d2) pool[d2] = mix32(pool[d2], hashmix(pool[s], hc));
  uint32_t hc2 = 0x8b51f9ddu; uint32_t w[8];
  for (int i = 0; i < 8; ++i) {
    uint32_t dv = pool[i & 3];
    dv ^= hc2; hc2 *= 0x58f38dedu; dv *= hc2; dv ^= dv >> 16; w[i] = dv;
  }
  u128 initstate = (((u128)((uint64_t)w[0] | ((uint64_t)w[1] << 32))) << 64) |
                   ((uint64_t)w[2] | ((uint64_t)w[3] << 32));
  u128 initseq   = (((u128)((uint64_t)w[4] | ((uint64_t)w[5] << 32))) << 64) |
                   ((uint64_t)w[6] | ((uint64_t)w[7] << 32));
  inc = (initseq << 1) | (u128)1;
  state = inc; state += initstate;
  state = state * PCG_MULT() + inc;
}
DEV u128 pcg_advance(u128 state, u128 inc, uint64_t delta) {
  u128 cm = PCG_MULT(), cp = inc, am = (u128)1, ap = (u128)0;
  while (delta) {
    if (delta & 1) { am = am * cm; ap = ap * cm + cp; }
    cp = (cm + (u128)1) * cp; cm = cm * cm; delta >>= 1;
  }
  return am * state + ap;
}
DEV uint64_t pcg_out(u128 st) {
  unsigned rot = (unsigned)(st >> 122);
  uint64_t x = (uint64_t)(st >> 64) ^ (uint64_t)st;
  return (x >> rot) | (x << ((64 - rot) & 63));
}
DEV uint64_t draw64(u128 s0, u128 inc, uint64_t k) {
  return pcg_out(pcg_advance(s0, inc, k + 1));
}
DEV uint32_t draw32(u128 s0, u128 inc, uint64_t j) {
  uint64_t v = draw64(s0, inc, j >> 1);
  return (j & 1) ? (uint32_t)(v >> 32) : (uint32_t)v;
}

// ---------------- config kernels ----------------
__global__ void cfg1_kernel() {
  int j = blockIdx.x * blockDim.x + threadIdx.x;
  if (j >= 20048) return;
  u128 s0, inc; pcg_seed(s0, inc);
  unsigned int u = draw32(s0, inc, (uint64_t)j);
  if (j < 10000) {
    g_is9[j] = (unsigned char)(u >> 31);           // Lemire rng_excl=2
  } else {
    int c = j - 10000;                             // Lemire rng_excl=6
    unsigned long long m = (unsigned long long)u * 6ull;
    g_cand[c] = (unsigned int)(m >> 32);
    g_accept[c] = ((unsigned int)m >= 4u) ? 1 : 0;
  }
}
__global__ void cfg2_kernel() {
  __shared__ int wsum[32];
  int t = threadIdx.x;                // 1024 threads, 1 block
  const int PER = 10;
  int base = t * PER;
  unsigned char acc[PER]; int cnt = 0;
  for (int k = 0; k < PER; ++k) {
    int idx = base + k;
    unsigned char a = (idx < 10048) ? g_accept[idx] : (unsigned char)0;
    acc[k] = a; cnt += a;
  }
  int lane = t & 31, wid = t >> 5;
  int inc = cnt;
  for (int o = 1; o < 32; o <<= 1) {
    int n = __shfl_up_sync(0xffffffffu, inc, o);
    if (lane >= o) inc += n;
  }
  if (lane == 31) wsum[wid] = inc;
  __syncthreads();
  if (wid == 0) {
    int v = wsum[lane];
    for (int o = 1; o < 32; o <<= 1) {
      int n = __shfl_up_sync(0xffffffffu, v, o);
      if (lane >= o) v += n;
    }
    wsum[lane] = v;
  }
  __syncthreads();
  int excl = inc - cnt + (wid ? wsum[wid - 1] : 0);
  for (int k = 0; k < PER; ++k) {
    int idx = base + k;
    if (idx < 10048 && acc[k]) {
      if (excl < 10000) {
        g_group[excl] = (unsigned char)(g_is9[excl] * 6 + g_cand[idx]);
        if (excl == 9999) {
          unsigned long long total32 = 10000ull + (unsigned long long)(idx + 1);
          g_D[0] = (total32 + 1ull) >> 1;
        }
      }
      ++excl;
    }
  }
}
__global__ void cfg3_kernel() {
  int i = blockIdx.x * blockDim.x + threadIdx.x;
  if (i >= 10000) return;
  u128 s0, inc; pcg_seed(s0, inc);
  unsigned long long u = draw64(s0, inc, g_D[0] + (unsigned long long)i);
  double dv = (double)(u >> 11) * (1.0 / 9007199254740992.0);
  g_bias[i] = (float)(-1.0 + 2.0 * dv);
}

// ---------------- channel sum (1 float4/thread, 1024 blocks — measured best) ----------------
__global__ void sum_kernel(const float* __restrict__ x) {
  int idx = blockIdx.x * blockDim.x + threadIdx.x;
  if (idx >= 256 * 1024) return;
  int b = idx >> 10, l4 = idx & 1023;
  const float4* xb = (const float4*)(x + (size_t)b * 23 * 4096) + l4;
  float4 a = xb[0];
#pragma unroll
  for (int c = 1; c < 23; ++c) {
    float4 v = xb[(size_t)c * 1024];
    a.x += v.x; a.y += v.y; a.z += v.z; a.w += v.w;
  }
  ((float4*)g_s)[(size_t)b * 1024 + l4] = a;
}

// ---------------- order-statistic helpers ----------------
DEV unsigned int f2ord(float f) {
  unsigned int b = __float_as_uint(f);
  return (b & 0x80000000u) ? ~b : (b | 0x80000000u);
}

template <int K, int D>
DEV void conv16(const float* S, int t, float* racc) {
  const int pad = ((K - 1) * D) >> 1;
#pragma unroll
  for (int i = 0; i < 16; ++i) {
    int s0 = t + i * 256 + 128 - pad;
    float acc = 0.f;
#pragma unroll
    for (int k = 0; k < K; ++k) acc += S[s0 + k * D];
    racc[i] = acc;
  }
}

// ---------------- main per-(batch,group) kernel ----------------
// Hot path: conv + max + pass0 histogram (registers only, no key store);
// flag=1 certified when no 8-bit bucket holds >=1353 keys (q66==q33 needs a
// value duplicated >=1353 times). Exact radix-select fallback otherwise.
__global__ void __launch_bounds__(256) main_kernel() {
  __shared__ __align__(16) unsigned int buf[4352];  // pad128 | data4096 | pad128
  __shared__ unsigned int histA[256];
  __shared__ unsigned int wt[8];
  __shared__ int sel[2];
  __shared__ float redf[8];
  __shared__ unsigned int smax[8];
  __shared__ int rci[8];

  int b = blockIdx.x, g = blockIdx.y;
  int t = threadIdx.x, lane = t & 31, wid = t >> 5;

  float* S = (float*)buf;
  unsigned int* U = buf + 128;

  histA[t] = 0;
  if (t < 128) buf[t] = 0; else buf[4096 + t] = 0;   // zero both pads
  {
    const float4* src = (const float4*)(g_s + (size_t)b * 4096);
    float4* dstS = (float4*)(S + 128);
#pragma unroll
    for (int i = 0; i < 4; ++i) dstS[t + i * 256] = src[t + i * 256];
  }
  __syncthreads();

  float racc[16];
  switch (g) {
    case 0:  conv16<7, 1>(S, t, racc);  break;
    case 1:  conv16<7, 2>(S, t, racc);  break;
    case 2:  conv16<7, 4>(S, t, racc);  break;
    case 3:  conv16<7, 8>(S, t, racc);  break;
    case 4:  conv16<7, 16>(S, t, racc); break;
    case 5:  conv16<7, 32>(S, t, racc); break;
    case 6:  conv16<9, 1>(S, t, racc);  break;
    case 7:  conv16<9, 2>(S, t, racc);  break;
    case 8:  conv16<9, 4>(S, t, racc);  break;
    case 9:  conv16<9, 8>(S, t, racc);  break;
    case 10: conv16<9, 16>(S, t, racc); break;
    default: conv16<9, 32>(S, t, racc); break;
  }

  // pass-0 histogram + block max, all from registers (no key store)
  float mx = -3.402823466e38f;
#pragma unroll
  for (int i = 0; i < 16; ++i) {
    float acc = racc[i];
    mx = fmaxf(mx, acc);
    unsigned int bucket = f2ord(acc) >> 24;
    unsigned int same = __match_any_sync(0xffffffffu, bucket);
    int ldr = __ffs(same) - 1;
    if (lane == ldr) atomicAdd(&histA[bucket], (unsigned int)__popc(same));
  }
  for (int o = 16; o; o >>= 1) mx = fmaxf(mx, __shfl_xor_sync(0xffffffffu, mx, o));
  if (lane == 0) redf[wid] = mx;
  __syncthreads();

  // max bucket count
  unsigned int hv = histA[t];
  for (int o = 16; o; o >>= 1) hv = max(hv, __shfl_xor_sync(0xffffffffu, hv, o));
  if (lane == 0) smax[wid] = hv;
  __syncthreads();
  unsigned int mb = 0;
#pragma unroll
  for (int i = 0; i < 8; ++i) mb = max(mb, smax[i]);

  if (mb < 1353u) {                 // certified: no value has 1353 duplicates
    if (t == 0) {
      float bm = redf[0];
#pragma unroll
      for (int i = 1; i < 8; ++i) bm = fmaxf(bm, redf[i]);
      g_m[b * 12 + g] = bm;
      g_t[b * 12 + g] = 1.0f;
    }
    return;
  }

  // ---- exact cold fallback: store keys (overwriting S), radix-select rank
  // 1351, then count(<= key). flag = (count < 2704) i.e. v[1351] < v[2703].
  __syncthreads();                   // all conv reads of S done
#pragma unroll
  for (int i = 0; i < 16; ++i) U[t + i * 256] = f2ord(racc[i]);
  __syncthreads();

#define SCAN_SELECT(rr)                                                        \
  {                                                                            \
    unsigned int oa = histA[t]; unsigned int a = oa;                           \
    for (int o = 1; o < 32; o <<= 1) {                                         \
      unsigned int na = __shfl_up_sync(0xffffffffu, a, o);                     \
      if (lane >= o) a += na;                                                  \
    }                                                                          \
    if (lane == 31) wt[wid] = a;                                               \
    __syncthreads();                                                           \
    if (wid == 0) {                                                            \
      unsigned int va = (lane < 8) ? wt[lane] : 0u;                            \
      for (int o = 1; o < 8; o <<= 1) {                                        \
        unsigned int na = __shfl_up_sync(0xffffffffu, va, o);                  \
        if (lane >= o) va += na;                                               \
      }                                                                        \
      if (lane < 8) wt[lane] = va;                                             \
    }                                                                          \
    __syncthreads();                                                           \
    a += wid ? wt[wid - 1] : 0u;                                               \
    unsigned int lo = a - oa;                                                  \
    if ((unsigned)(rr) >= lo && (unsigned)(rr) < a) { sel[0] = t; sel[1] = (int)lo; } \
    __syncthreads();                                                           \
  }

  int rA = 1351; unsigned int pA = 0;
  SCAN_SELECT(rA);
  pA = ((unsigned int)sel[0]) << 24; rA -= sel[1];

  for (int p = 1; p < 4; ++p) {
    int shift = 24 - 8 * p;
    unsigned int maskHi = 0xFFFFFFFFu << (32 - 8 * p);
    histA[t] = 0;
    __syncthreads();
#pragma unroll
    for (int i = 0; i < 16; ++i) {
      unsigned int key = U[t + i * 256];
      bool ok = ((key ^ pA) & maskHi) == 0;
      unsigned int bucket = (key >> shift) & 255u;
      unsigned int act = __ballot_sync(0xffffffffu, ok);
      if (ok) {
        unsigned int same = __match_any_sync(act, bucket);
        int ldr = __ffs(same) - 1;
        if (lane == ldr) atomicAdd(&histA[bucket], (unsigned int)__popc(same));
      }
    }
    __syncthreads();
    SCAN_SELECT(rA);
    pA |= ((unsigned int)sel[0]) << shift; rA -= sel[1];
  }

  int cnt = 0;
#pragma unroll
  for (int i = 0; i < 16; ++i) cnt += (U[t + i * 256] <= pA) ? 1 : 0;
  for (int o = 16; o; o >>= 1) cnt += __shfl_xor_sync(0xffffffffu, cnt, o);
  if (lane == 0) rci[wid] = cnt;
  __syncthreads();
  if (t == 0) {
    int total = 0;
    float bm = redf[0];
#pragma unroll
    for (int i = 0; i < 8; ++i) { total += rci[i]; bm = fmaxf(bm, redf[i]); }
    g_m[b * 12 + g] = bm;
    g_t[b * 12 + g] = (total < 2704) ? 1.0f : 0.0f;
  }
}

// ---------------- output writer (float4 = 2 feature pairs) ----------------
__global__ void out_kernel(float* __restrict__ out) {
  int idx = blockIdx.x * blockDim.x + threadIdx.x;   // b*5000 + j
  if (idx >= 1280000) return;
  int b = idx / 5000;
  int j = idx - b * 5000;
  int i0 = 2 * j, i1 = 2 * j + 1;
  int g0 = g_group[i0], g1 = g_group[i1];
  float4 v;
  v.x = (g_m[b * 12 + g0] > g_bias[i0]) ? 1.0f : 0.0f;
  v.y = g_t[b * 12 + g0];
  v.z = (g_m[b * 12 + g1] > g_bias[i1]) ? 1.0f : 0.0f;
  v.w = g_t[b * 12 + g1];
  ((float4*)out)[idx] = v;
}

extern "C" void kernel_launch(void* const* d_in, const int* in_sizes, int n_in,
                              void* d_out, int out_size) {
  const float* x = (const float*)d_in[0];
  float* out = (float*)d_out;
  cfg1_kernel<<<(20048 + 255) / 256, 256>>>();
  cfg2_kernel<<<1, 1024>>>();
  cfg3_kernel<<<(10000 + 255) / 256, 256>>>();
  sum_kernel<<<(256 * 1024 + 255) / 256, 256>>>(x);
  main_kernel<<<dim3(256, 12), 256>>>();
  out_kernel<<<(1280000 + 255) / 256, 256>>>(out);
}

// round 6
// speedup vs baseline: 4.6224x; 1.0436x over previous
#include <cuda_runtime.h>
#include <cstdint>

#define DEV static __device__ __forceinline__
typedef unsigned __int128 u128;

__device__ float g_s[256 * 4096];
__device__ float g_m[256 * 12];
__device__ float g_t[256 * 12];
__device__ unsigned char g_is9[10000];
__device__ unsigned char g_group[10000];
__device__ float g_bias[10000];
__device__ unsigned int g_cand[10048];
__device__ unsigned char g_accept[10048];
__device__ unsigned long long g_D[1];

// ---------------- PCG64 (numpy default_rng) ----------------
DEV u128 PCG_MULT() {
  return (((u128)0x2360ED051FC65DA4ULL) << 64) | 0x4385DF649FCCF645ULL;
}
DEV uint32_t hashmix(uint32_t v, uint32_t& hc) {
  v ^= hc; hc *= 0x931e8875u; v *= hc; v ^= v >> 16; return v;
}
DEV uint32_t mix32(uint32_t x, uint32_t y) {
  uint32_t r = 0xca01f9ddu * x - 0x4973f715u * y; r ^= r >> 16; return r;
}
DEV void pcg_seed(u128& state, u128& inc) {
  uint32_t pool[4]; uint32_t hc = 0x43b0d7e5u;
  for (int i = 0; i < 4; ++i) pool[i] = hashmix(0u, hc);
  for (int s = 0; s < 4; ++s)
    for (int d2 = 0; d2 < 4; ++d2)
      if (s != d2) pool[d2] = mix32(pool[d2], hashmix(pool[s], hc));
  uint32_t hc2 = 0x8b51f9ddu; uint32_t w[8];
  for (int i = 0; i < 8; ++i) {
    uint32_t dv = pool[i & 3];
    dv ^= hc2; hc2 *= 0x58f38dedu; dv *= hc2; dv ^= dv >> 16; w[i] = dv;
  }
  u128 initstate = (((u128)((uint64_t)w[0] | ((uint64_t)w[1] << 32))) << 64) |
                   ((uint64_t)w[2] | ((uint64_t)w[3] << 32));
  u128 initseq   = (((u128)((uint64_t)w[4] | ((uint64_t)w[5] << 32))) << 64) |
                   ((uint64_t)w[6] | ((uint64_t)w[7] << 32));
  inc = (initseq << 1) | (u128)1;
  state = inc; state += initstate;
  state = state * PCG_MULT() + inc;
}
DEV u128 pcg_advance(u128 state, u128 inc, uint64_t delta) {
  u128 cm = PCG_MULT(), cp = inc, am = (u128)1, ap = (u128)0;
  while (delta) {
    if (delta & 1) { am = am * cm; ap = ap * cm + cp; }
    cp = (cm + (u128)1) * cp; cm = cm * cm; delta >>= 1;
  }
  return am * state + ap;
}
DEV uint64_t pcg_out(u128 st) {
  unsigned rot = (unsigned)(st >> 122);
  uint64_t x = (uint64_t)(st >> 64) ^ (uint64_t)st;
  return (x >> rot) | (x << ((64 - rot) & 63));
}
DEV uint64_t draw64(u128 s0, u128 inc, uint64_t k) {
  return pcg_out(pcg_advance(s0, inc, k + 1));
}
DEV uint32_t draw32(u128 s0, u128 inc, uint64_t j) {
  uint64_t v = draw64(s0, inc, j >> 1);
  return (j & 1) ? (uint32_t)(v >> 32) : (uint32_t)v;
}

// ---------------- config kernels ----------------
__global__ void cfg1_kernel() {
  int j = blockIdx.x * blockDim.x + threadIdx.x;
  if (j >= 20048) return;
  u128 s0, inc; pcg_seed(s0, inc);
  unsigned int u = draw32(s0, inc, (uint64_t)j);
  if (j < 10000) {
    g_is9[j] = (unsigned char)(u >> 31);           // Lemire rng_excl=2
  } else {
    int c = j - 10000;                             // Lemire rng_excl=6
    unsigned long long m = (unsigned long long)u * 6ull;
    g_cand[c] = (unsigned int)(m >> 32);
    g_accept[c] = ((unsigned int)m >= 4u) ? 1 : 0;
  }
}
__global__ void cfg2_kernel() {
  __shared__ int wsum[32];
  int t = threadIdx.x;                // 1024 threads, 1 block
  const int PER = 10;
  int base = t * PER;
  unsigned char acc[PER]; int cnt = 0;
  for (int k = 0; k < PER; ++k) {
    int idx = base + k;
    unsigned char a = (idx < 10048) ? g_accept[idx] : (unsigned char)0;
    acc[k] = a; cnt += a;
  }
  int lane = t & 31, wid = t >> 5;
  int inc = cnt;
  for (int o = 1; o < 32; o <<= 1) {
    int n = __shfl_up_sync(0xffffffffu, inc, o);
    if (lane >= o) inc += n;
  }
  if (lane == 31) wsum[wid] = inc;
  __syncthreads();
  if (wid == 0) {
    int v = wsum[lane];
    for (int o = 1; o < 32; o <<= 1) {
      int n = __shfl_up_sync(0xffffffffu, v, o);
      if (lane >= o) v += n;
    }
    wsum[lane] = v;
  }
  __syncthreads();
  int excl = inc - cnt + (wid ? wsum[wid - 1] : 0);
  for (int k = 0; k < PER; ++k) {
    int idx = base + k;
    if (idx < 10048 && acc[k]) {
      if (excl < 10000) {
        g_group[excl] = (unsigned char)(g_is9[excl] * 6 + g_cand[idx]);
        if (excl == 9999) {
          unsigned long long total32 = 10000ull + (unsigned long long)(idx + 1);
          g_D[0] = (total32 + 1ull) >> 1;
        }
      }
      ++excl;
    }
  }
}
__global__ void cfg3_kernel() {
  int i = blockIdx.x * blockDim.x + threadIdx.x;
  if (i >= 10000) return;
  u128 s0, inc; pcg_seed(s0, inc);
  unsigned long long u = draw64(s0, inc, g_D[0] + (unsigned long long)i);
  double dv = (double)(u >> 11) * (1.0 / 9007199254740992.0);
  g_bias[i] = (float)(-1.0 + 2.0 * dv);
}

// ---------------- channel sum ----------------
__global__ void sum_kernel(const float* __restrict__ x) {
  int idx = blockIdx.x * blockDim.x + threadIdx.x;
  if (idx >= 256 * 1024) return;
  int b = idx >> 10, l4 = idx & 1023;
  const float4* xb = (const float4*)(x + (size_t)b * 23 * 4096) + l4;
  float4 a = __ldcs(xb);
#pragma unroll
  for (int c = 1; c < 23; ++c) {
    float4 v = __ldcs(xb + (size_t)c * 1024);
    a.x += v.x; a.y += v.y; a.z += v.z; a.w += v.w;
  }
  ((float4*)g_s)[(size_t)b * 1024 + l4] = a;
}

// ---------------- order-statistic helpers ----------------
DEV unsigned int f2ord(float f) {
  unsigned int b = __float_as_uint(f);
  return (b & 0x80000000u) ? ~b : (b | 0x80000000u);
}

// dual-K conv for one dilation: r7 = 7-tap, r9 = r7 + outer two taps
template <int D>
DEV void conv2K(const float* S, int t, float* r7, float* r9) {
#pragma unroll
  for (int i = 0; i < 16; ++i) {
    int l = t + i * 256 + 128;
    float a = S[l - 3 * D];
    a += S[l - 2 * D]; a += S[l - D]; a += S[l]; a += S[l + D];
    a += S[l + 2 * D]; a += S[l + 3 * D];
    r7[i] = a;
    r9[i] = a + S[l - 4 * D] + S[l + 4 * D];
  }
}

// cold exact fallback: keys already stored in U, hist holds pass-0 counts.
// radix-select rank 1351, count(<=key); flag = count < 2704 (v[1351] < v[2703]).
__device__ __noinline__ void fallback_select(unsigned int* U, unsigned int* hist,
                                             unsigned int* wt, int* sel, int* rci,
                                             int t, int gi) {
  int lane = t & 31, wid = t >> 5;

#define SCAN_SELECT(rr)                                                        \
  {                                                                            \
    unsigned int oa = hist[t]; unsigned int a = oa;                            \
    for (int o = 1; o < 32; o <<= 1) {                                         \
      unsigned int na = __shfl_up_sync(0xffffffffu, a, o);                     \
      if (lane >= o) a += na;                                                  \
    }                                                                          \
    if (lane == 31) wt[wid] = a;                                               \
    __syncthreads();                                                           \
    if (wid == 0) {                                                            \
      unsigned int va = (lane < 8) ? wt[lane] : 0u;                            \
      for (int o = 1; o < 8; o <<= 1) {                                        \
        unsigned int na = __shfl_up_sync(0xffffffffu, va, o);                  \
        if (lane >= o) va += na;                                               \
      }                                                                        \
      if (lane < 8) wt[lane] = va;                                             \
    }                                                                          \
    __syncthreads();                                                           \
    a += wid ? wt[wid - 1] : 0u;                                               \
    unsigned int lo = a - oa;                                                  \
    if ((unsigned)(rr) >= lo && (unsigned)(rr) < a) { sel[0] = t; sel[1] = (int)lo; } \
    __syncthreads();                                                           \
  }

  int rA = 1351; unsigned int pA = 0;
  SCAN_SELECT(rA);
  pA = ((unsigned int)sel[0]) << 24; rA -= sel[1];

  for (int p = 1; p < 4; ++p) {
    int shift = 24 - 8 * p;
    unsigned int maskHi = 0xFFFFFFFFu << (32 - 8 * p);
    hist[t] = 0;
    __syncthreads();
#pragma unroll
    for (int i = 0; i < 16; ++i) {
      unsigned int key = U[t + i * 256];
      bool ok = ((key ^ pA) & maskHi) == 0;
      unsigned int bucket = (key >> shift) & 255u;
      unsigned int act = __ballot_sync(0xffffffffu, ok);
      if (ok) {
        unsigned int same = __match_any_sync(act, bucket);
        int ldr = __ffs(same) - 1;
        if (lane == ldr) atomicAdd(&hist[bucket], (unsigned int)__popc(same));
      }
    }
    __syncthreads();
    SCAN_SELECT(rA);
    pA |= ((unsigned int)sel[0]) << shift; rA -= sel[1];
  }

  int cnt = 0;
#pragma unroll
  for (int i = 0; i < 16; ++i) cnt += (U[t + i * 256] <= pA) ? 1 : 0;
  for (int o = 16; o; o >>= 1) cnt += __shfl_xor_sync(0xffffffffu, cnt, o);
  if (lane == 0) rci[wid] = cnt;
  __syncthreads();
  if (t == 0) {
    int total = 0;
#pragma unroll
    for (int i = 0; i < 8; ++i) total += rci[i];
    g_t[gi] = (total < 2704) ? 1.0f : 0.0f;
  }
#undef SCAN_SELECT
}

// ---------------- main per-(batch,dilation) kernel: both K=7 and K=9 ----------------
__global__ void __launch_bounds__(256) main_kernel() {
  __shared__ __align__(16) unsigned int buf[4352];  // pad128 | data4096 | pad128
  __shared__ unsigned int histA[256], histB[256];
  __shared__ unsigned int wt[8];
  __shared__ int sel[2];
  __shared__ float redfA[8], redfB[8];
  __shared__ unsigned int smaxA[8], smaxB[8];
  __shared__ int rci[8];

  int b = blockIdx.x, dexp = blockIdx.y;
  int t = threadIdx.x, lane = t & 31, wid = t >> 5;

  float* S = (float*)buf;
  unsigned int* U = buf + 128;

  histA[t] = 0; histB[t] = 0;
  if (t < 128) buf[t] = 0; else buf[4096 + t] = 0;
  {
    const float4* src = (const float4*)(g_s + (size_t)b * 4096);
    float4* dstS = (float4*)(S + 128);
#pragma unroll
    for (int i = 0; i < 4; ++i) dstS[t + i * 256] = src[t + i * 256];
  }
  __syncthreads();

  float r7[16], r9[16];
  switch (dexp) {
    case 0:  conv2K<1>(S, t, r7, r9);  break;
    case 1:  conv2K<2>(S, t, r7, r9);  break;
    case 2:  conv2K<4>(S, t, r7, r9);  break;
    case 3:  conv2K<8>(S, t, r7, r9);  break;
    case 4:  conv2K<16>(S, t, r7, r9); break;
    default: conv2K<32>(S, t, r7, r9); break;
  }

  // register-only: maxes + pass-0 histograms for both groups
  float mxA = -3.402823466e38f, mxB = -3.402823466e38f;
#pragma unroll
  for (int i = 0; i < 16; ++i) {
    float a = r7[i], c = r9[i];
    mxA = fmaxf(mxA, a); mxB = fmaxf(mxB, c);
    unsigned int bA = f2ord(a) >> 24;
    unsigned int sameA = __match_any_sync(0xffffffffu, bA);
    if (lane == __ffs(sameA) - 1) atomicAdd(&histA[bA], (unsigned int)__popc(sameA));
    unsigned int bB = f2ord(c) >> 24;
    unsigned int sameB = __match_any_sync(0xffffffffu, bB);
    if (lane == __ffs(sameB) - 1) atomicAdd(&histB[bB], (unsigned int)__popc(sameB));
  }
  for (int o = 16; o; o >>= 1) {
    mxA = fmaxf(mxA, __shfl_xor_sync(0xffffffffu, mxA, o));
    mxB = fmaxf(mxB, __shfl_xor_sync(0xffffffffu, mxB, o));
  }
  if (lane == 0) { redfA[wid] = mxA; redfB[wid] = mxB; }
  __syncthreads();

  unsigned int hA = histA[t], hB = histB[t];
  for (int o = 16; o; o >>= 1) {
    hA = max(hA, __shfl_xor_sync(0xffffffffu, hA, o));
    hB = max(hB, __shfl_xor_sync(0xffffffffu, hB, o));
  }
  if (lane == 0) { smaxA[wid] = hA; smaxB[wid] = hB; }
  __syncthreads();

  unsigned int mbA = 0, mbB = 0;
#pragma unroll
  for (int i = 0; i < 8; ++i) { mbA = max(mbA, smaxA[i]); mbB = max(mbB, smaxB[i]); }
  bool fbA = (mbA >= 1353u), fbB = (mbB >= 1353u);

  int giA = b * 12 + dexp, giB = b * 12 + 6 + dexp;
  if (t == 0) {
    float bmA = redfA[0], bmB = redfB[0];
#pragma unroll
    for (int i = 1; i < 8; ++i) { bmA = fmaxf(bmA, redfA[i]); bmB = fmaxf(bmB, redfB[i]); }
    g_m[giA] = bmA; g_m[giB] = bmB;
    if (!fbA) g_t[giA] = 1.0f;      // certified: no 1353-duplicate value
    if (!fbB) g_t[giB] = 1.0f;
  }

  if (fbA) {
    __syncthreads();
#pragma unroll
    for (int i = 0; i < 16; ++i) U[t + i * 256] = f2ord(r7[i]);
    __syncthreads();
    fallback_select(U, histA, wt, sel, rci, t, giA);
  }
  if (fbB) {
    __syncthreads();
#pragma unroll
    for (int i = 0; i < 16; ++i) U[t + i * 256] = f2ord(r9[i]);
    __syncthreads();
    fallback_select(U, histB, wt, sel, rci, t, giB);
  }
}

// ---------------- output writer (float4 = 2 feature pairs) ----------------
__global__ void out_kernel(float* __restrict__ out) {
  int idx = blockIdx.x * blockDim.x + threadIdx.x;   // b*5000 + j
  if (idx >= 1280000) return;
  int b = idx / 5000;
  int j = idx - b * 5000;
  int i0 = 2 * j, i1 = 2 * j + 1;
  int g0 = g_group[i0], g1 = g_group[i1];
  float4 v;
  v.x = (g_m[b * 12 + g0] > g_bias[i0]) ? 1.0f : 0.0f;
  v.y = g_t[b * 12 + g0];
  v.z = (g_m[b * 12 + g1] > g_bias[i1]) ? 1.0f : 0.0f;
  v.w = g_t[b * 12 + g1];
  ((float4*)out)[idx] = v;
}

extern "C" void kernel_launch(void* const* d_in, const int* in_sizes, int n_in,
                              void* d_out, int out_size) {
  const float* x = (const float*)d_in[0];
  float* out = (float*)d_out;
  cfg1_kernel<<<(20048 + 255) / 256, 256>>>();
  cfg2_kernel<<<1, 1024>>>();
  cfg3_kernel<<<(10000 + 255) / 256, 256>>>();
  sum_kernel<<<(256 * 1024 + 255) / 256, 256>>>(x);
  main_kernel<<<dim3(256, 6), 256>>>();
  out_kernel<<<(1280000 + 255) / 256, 256>>>(out);
}